// round 1
// baseline (speedup 1.0000x reference)
#include <cuda_runtime.h>
#include <math.h>

#define BATCH 8
#define LSEQ  1024
#define HID   768
#define NH    12
#define DH    64
#define MLPD  3072
#define MROWS (BATCH*LSEQ)   // 8192
#define NHEADS_TOT (BATCH*NH) // 96

// ---------------- static scratch (no allocations allowed) ----------------
__device__ float g_Q  [MROWS*HID];
__device__ float g_K  [MROWS*HID];
__device__ float g_Qh [MROWS*HID];
__device__ float g_Kh [MROWS*HID];
__device__ float g_S  [(size_t)NHEADS_TOT*LSEQ*LSEQ];   // 402 MB
__device__ float g_Ch [MROWS*HID];   // head-major ctx
__device__ float g_Ctx[MROWS*HID];   // interleaved ctx
__device__ float g_y  [MROWS*HID];
__device__ float g_x1 [MROWS*HID];
__device__ float g_Hf [(size_t)MROWS*MLPD];              // 100 MB
__device__ float g_y2 [MROWS*HID];

// ---------------- helpers ----------------
__device__ __forceinline__ float gelu_f(float v) {
    return 0.5f * v * (1.0f + erff(v * 0.7071067811865475f));
}

enum { EPI_NONE = 0, EPI_RES = 1, EPI_BIAS_GELU = 2, EPI_BIAS_RES = 3 };

// ---------------- generic 128x128x8 SGEMM, C = A(MxK) @ B(KxN) ----------------
template<int EPI>
__global__ __launch_bounds__(256) void sgemm128(
    const float* __restrict__ A, const float* __restrict__ B, float* __restrict__ C,
    const float* __restrict__ bias, const float* __restrict__ res,
    int M, int N, int K)
{
    __shared__ float As[8][128];
    __shared__ float Bs[8][128];

    const int tid = threadIdx.x;
    const int bx = blockIdx.x;   // N tile
    const int by = blockIdx.y;   // M tile

    // A tile load: 128 rows x 8 cols -> 256 float4 (2 float4 per row)
    const int arow = tid >> 1;
    const int acol = (tid & 1) * 4;
    // B tile load: 8 rows x 128 cols -> 256 float4
    const int brow = tid >> 5;
    const int bcol = (tid & 31) * 4;

    const float* Aptr = A + (size_t)(by * 128 + arow) * K + acol;
    const float* Bptr = B + (size_t)brow * N + bx * 128 + bcol;

    const int trow = (tid >> 4) * 8;
    const int tcol = (tid & 15) * 8;

    float acc[8][8];
    #pragma unroll
    for (int i = 0; i < 8; i++)
        #pragma unroll
        for (int j = 0; j < 8; j++) acc[i][j] = 0.0f;

    for (int k0 = 0; k0 < K; k0 += 8) {
        float4 a4 = *(const float4*)Aptr;  Aptr += 8;
        float4 b4 = *(const float4*)Bptr;  Bptr += (size_t)8 * N;
        As[acol + 0][arow] = a4.x;
        As[acol + 1][arow] = a4.y;
        As[acol + 2][arow] = a4.z;
        As[acol + 3][arow] = a4.w;
        *(float4*)&Bs[brow][bcol] = b4;
        __syncthreads();

        #pragma unroll
        for (int k = 0; k < 8; k++) {
            float ar[8], br[8];
            *(float4*)(ar)     = *(const float4*)&As[k][trow];
            *(float4*)(ar + 4) = *(const float4*)&As[k][trow + 4];
            *(float4*)(br)     = *(const float4*)&Bs[k][tcol];
            *(float4*)(br + 4) = *(const float4*)&Bs[k][tcol + 4];
            #pragma unroll
            for (int i = 0; i < 8; i++)
                #pragma unroll
                for (int j = 0; j < 8; j++)
                    acc[i][j] = fmaf(ar[i], br[j], acc[i][j]);
        }
        __syncthreads();
    }

    const int crow0 = by * 128 + trow;
    const int ccol0 = bx * 128 + tcol;
    #pragma unroll
    for (int i = 0; i < 8; i++) {
        const size_t rbase = (size_t)(crow0 + i) * N;
        #pragma unroll
        for (int j = 0; j < 8; j++) {
            const int c = ccol0 + j;
            float v = acc[i][j];
            if (EPI == EPI_RES)        v += res[rbase + c];
            if (EPI == EPI_BIAS_GELU)  v = gelu_f(v + bias[c]);
            if (EPI == EPI_BIAS_RES)   v += bias[c] + res[rbase + c];
            C[rbase + c] = v;
        }
    }
}

// ---------------- permutes: interleaved (h = d*12 + n) <-> head-major ----------------
__global__ void to_head_k(const float* __restrict__ X, float* __restrict__ Xh) {
    int idx = blockIdx.x * blockDim.x + threadIdx.x;   // over head-major layout
    if (idx >= MROWS * HID) return;
    int d = idx & 63;
    int l = (idx >> 6) & 1023;
    int z = idx >> 16;                 // b*NH + n
    int n = z % NH, b = z / NH;
    Xh[idx] = X[(size_t)(b * LSEQ + l) * HID + d * NH + n];
}

__global__ void from_head_k(const float* __restrict__ Xh, float* __restrict__ X) {
    int idx = blockIdx.x * blockDim.x + threadIdx.x;   // over interleaved layout
    if (idx >= MROWS * HID) return;
    int h = idx % HID;
    int row = idx / HID;
    int l = row & 1023, b = row >> 10;
    int d = h / NH, n = h % NH;
    X[idx] = Xh[((size_t)(b * NH + n) * LSEQ + l) * DH + d];
}

// ---------------- attention scores: S[z][l][m] = 0.125 * Qh[z][l]·Kh[z][m] ----------------
__global__ __launch_bounds__(256) void attn_scores_k(
    const float* __restrict__ Qh, const float* __restrict__ Kh, float* __restrict__ S)
{
    const int z = blockIdx.z;
    const int lt = blockIdx.y, mt = blockIdx.x;
    const float* Q  = Qh + ((size_t)z * LSEQ + lt * 64) * DH;
    const float* Kp = Kh + ((size_t)z * LSEQ + mt * 64) * DH;

    __shared__ float Qs[64][DH + 1];
    __shared__ float Ks[64][DH + 1];
    const int tid = threadIdx.x;

    for (int i = tid; i < 64 * 16; i += 256) {
        int r = i >> 4, c = (i & 15) << 2;
        float4 q4 = *(const float4*)(Q + r * DH + c);
        Qs[r][c] = q4.x; Qs[r][c+1] = q4.y; Qs[r][c+2] = q4.z; Qs[r][c+3] = q4.w;
        float4 k4 = *(const float4*)(Kp + r * DH + c);
        Ks[r][c] = k4.x; Ks[r][c+1] = k4.y; Ks[r][c+2] = k4.z; Ks[r][c+3] = k4.w;
    }
    __syncthreads();

    const int tr = (tid >> 4) << 2;
    const int tc = (tid & 15) << 2;
    float acc[4][4];
    #pragma unroll
    for (int i = 0; i < 4; i++)
        #pragma unroll
        for (int j = 0; j < 4; j++) acc[i][j] = 0.0f;

    #pragma unroll 8
    for (int d = 0; d < DH; d++) {
        float q[4], k[4];
        #pragma unroll
        for (int i = 0; i < 4; i++) q[i] = Qs[tr + i][d];
        #pragma unroll
        for (int j = 0; j < 4; j++) k[j] = Ks[tc + j][d];
        #pragma unroll
        for (int i = 0; i < 4; i++)
            #pragma unroll
            for (int j = 0; j < 4; j++)
                acc[i][j] = fmaf(q[i], k[j], acc[i][j]);
    }

    float* Sp = S + (size_t)z * LSEQ * LSEQ;
    #pragma unroll
    for (int i = 0; i < 4; i++)
        #pragma unroll
        for (int j = 0; j < 4; j++)
            Sp[(size_t)(lt * 64 + tr + i) * LSEQ + (mt * 64 + tc + j)] = acc[i][j] * 0.125f;
}

// ---------------- row softmax over 1024 columns ----------------
__global__ __launch_bounds__(256) void softmax_rows_k(float* __restrict__ S) {
    float* p = S + (size_t)blockIdx.x * LSEQ;
    const int tid = threadIdx.x;
    __shared__ float sh[8];

    float m = -3.0e38f;
    for (int c = tid; c < LSEQ; c += 256) m = fmaxf(m, p[c]);
    #pragma unroll
    for (int o = 16; o; o >>= 1) m = fmaxf(m, __shfl_xor_sync(0xffffffffu, m, o));
    if ((tid & 31) == 0) sh[tid >> 5] = m;
    __syncthreads();
    if (tid == 0) {
        float v = sh[0];
        #pragma unroll
        for (int i = 1; i < 8; i++) v = fmaxf(v, sh[i]);
        sh[0] = v;
    }
    __syncthreads();
    m = sh[0];
    __syncthreads();

    float s = 0.0f;
    for (int c = tid; c < LSEQ; c += 256) {
        float e = expf(p[c] - m);
        p[c] = e;
        s += e;
    }
    #pragma unroll
    for (int o = 16; o; o >>= 1) s += __shfl_xor_sync(0xffffffffu, s, o);
    if ((tid & 31) == 0) sh[tid >> 5] = s;
    __syncthreads();
    if (tid == 0) {
        float v = 0.0f;
        #pragma unroll
        for (int i = 0; i < 8; i++) v += sh[i];
        sh[0] = v;
    }
    __syncthreads();
    const float inv = 1.0f / sh[0];
    for (int c = tid; c < LSEQ; c += 256) p[c] *= inv;
}

// ---------------- ctx: Ch[z][l][d] = sum_m P[z][l][m] * Kh[z][m][d] ----------------
__global__ __launch_bounds__(256) void attn_ctx_k(
    const float* __restrict__ S, const float* __restrict__ Kh, float* __restrict__ Ch)
{
    const int z = blockIdx.y;
    const int lt = blockIdx.x;
    const float* Sp = S + (size_t)z * LSEQ * LSEQ + (size_t)(lt * 64) * LSEQ;
    const float* Kp = Kh + (size_t)z * LSEQ * DH;

    __shared__ float Ps[64][33];
    __shared__ float Ks[32][DH + 1];
    const int tid = threadIdx.x;
    const int tr = (tid >> 4) << 2;
    const int tc = (tid & 15) << 2;

    float acc[4][4];
    #pragma unroll
    for (int i = 0; i < 4; i++)
        #pragma unroll
        for (int j = 0; j < 4; j++) acc[i][j] = 0.0f;

    for (int m0 = 0; m0 < LSEQ; m0 += 32) {
        for (int i = tid; i < 64 * 8; i += 256) {
            int r = i >> 3, c = (i & 7) << 2;
            float4 v = *(const float4*)(Sp + (size_t)r * LSEQ + m0 + c);
            Ps[r][c] = v.x; Ps[r][c+1] = v.y; Ps[r][c+2] = v.z; Ps[r][c+3] = v.w;
        }
        for (int i = tid; i < 32 * 16; i += 256) {
            int r = i >> 4, c = (i & 15) << 2;
            float4 v = *(const float4*)(Kp + (size_t)(m0 + r) * DH + c);
            Ks[r][c] = v.x; Ks[r][c+1] = v.y; Ks[r][c+2] = v.z; Ks[r][c+3] = v.w;
        }
        __syncthreads();

        #pragma unroll
        for (int m = 0; m < 32; m++) {
            float pr[4], kr[4];
            #pragma unroll
            for (int i = 0; i < 4; i++) pr[i] = Ps[tr + i][m];
            #pragma unroll
            for (int j = 0; j < 4; j++) kr[j] = Ks[m][tc + j];
            #pragma unroll
            for (int i = 0; i < 4; i++)
                #pragma unroll
                for (int j = 0; j < 4; j++)
                    acc[i][j] = fmaf(pr[i], kr[j], acc[i][j]);
        }
        __syncthreads();
    }

    #pragma unroll
    for (int i = 0; i < 4; i++)
        #pragma unroll
        for (int j = 0; j < 4; j++)
            Ch[((size_t)z * LSEQ + lt * 64 + tr + i) * DH + tc + j] = acc[i][j];
}

// ---------------- layernorm over rows of 768 ----------------
__global__ __launch_bounds__(256) void layernorm_rows_k(
    const float* __restrict__ X, const float* __restrict__ g,
    const float* __restrict__ be, float* __restrict__ Y)
{
    const int row = blockIdx.x;
    const float* x = X + (size_t)row * HID;
    float* y = Y + (size_t)row * HID;
    const int tid = threadIdx.x;
    __shared__ float shs[8], shss[8];

    float s = 0.0f, ss = 0.0f;
    for (int c = tid; c < HID; c += 256) {
        float v = x[c];
        s += v;
        ss = fmaf(v, v, ss);
    }
    #pragma unroll
    for (int o = 16; o; o >>= 1) {
        s  += __shfl_xor_sync(0xffffffffu, s, o);
        ss += __shfl_xor_sync(0xffffffffu, ss, o);
    }
    if ((tid & 31) == 0) { shs[tid >> 5] = s; shss[tid >> 5] = ss; }
    __syncthreads();
    if (tid == 0) {
        float a = 0.0f, b = 0.0f;
        #pragma unroll
        for (int i = 0; i < 8; i++) { a += shs[i]; b += shss[i]; }
        shs[0] = a; shss[0] = b;
    }
    __syncthreads();
    const float mu  = shs[0]  * (1.0f / HID);
    const float var = shss[0] * (1.0f / HID) - mu * mu;
    const float inv = rsqrtf(var + 1e-5f);
    for (int c = tid; c < HID; c += 256)
        y[c] = (x[c] - mu) * inv * g[c] + be[c];
}

// ---------------- host launch ----------------
extern "C" void kernel_launch(void* const* d_in, const int* in_sizes, int n_in,
                              void* d_out, int out_size)
{
    const float* x   = (const float*)d_in[0];
    const float* Wq  = (const float*)d_in[1];
    const float* Wk  = (const float*)d_in[2];
    // d_in[3] = Wv: unused (ctx contracts with K in the reference)
    const float* Wo  = (const float*)d_in[4];
    const float* W1  = (const float*)d_in[5];
    const float* b1  = (const float*)d_in[6];
    const float* W2  = (const float*)d_in[7];
    const float* b2  = (const float*)d_in[8];
    const float* g1  = (const float*)d_in[9];
    const float* be1 = (const float*)d_in[10];
    const float* g2  = (const float*)d_in[11];
    const float* be2 = (const float*)d_in[12];
    float* out = (float*)d_out;

    float *Q, *K, *Qh, *Kh, *S, *Ch, *Ctx, *y, *x1, *Hf, *y2;
    cudaGetSymbolAddress((void**)&Q,  g_Q);
    cudaGetSymbolAddress((void**)&K,  g_K);
    cudaGetSymbolAddress((void**)&Qh, g_Qh);
    cudaGetSymbolAddress((void**)&Kh, g_Kh);
    cudaGetSymbolAddress((void**)&S,  g_S);
    cudaGetSymbolAddress((void**)&Ch, g_Ch);
    cudaGetSymbolAddress((void**)&Ctx,g_Ctx);
    cudaGetSymbolAddress((void**)&y,  g_y);
    cudaGetSymbolAddress((void**)&x1, g_x1);
    cudaGetSymbolAddress((void**)&Hf, g_Hf);
    cudaGetSymbolAddress((void**)&y2, g_y2);

    const int nperm = MROWS * HID;

    // Q = x @ Wq ; K = x @ Wk
    sgemm128<EPI_NONE><<<dim3(HID / 128, MROWS / 128), 256>>>(x, Wq, Q, nullptr, nullptr, MROWS, HID, HID);
    sgemm128<EPI_NONE><<<dim3(HID / 128, MROWS / 128), 256>>>(x, Wk, K, nullptr, nullptr, MROWS, HID, HID);

    // permute to head-major [b*12+n][l][d]  (h = d*12 + n)
    to_head_k<<<(nperm + 255) / 256, 256>>>(Q, Qh);
    to_head_k<<<(nperm + 255) / 256, 256>>>(K, Kh);

    // S = (Qh Kh^T) / 8 ; softmax over keys ; Ch = P @ Kh (K used as V per reference)
    attn_scores_k<<<dim3(LSEQ / 64, LSEQ / 64, NHEADS_TOT), 256>>>(Qh, Kh, S);
    softmax_rows_k<<<NHEADS_TOT * LSEQ, 256>>>(S);
    attn_ctx_k<<<dim3(LSEQ / 64, NHEADS_TOT), 256>>>(S, Kh, Ch);
    from_head_k<<<(nperm + 255) / 256, 256>>>(Ch, Ctx);

    // y = ctx @ Wo + x ; x1 = LN(y)
    sgemm128<EPI_RES><<<dim3(HID / 128, MROWS / 128), 256>>>(Ctx, Wo, y, nullptr, x, MROWS, HID, HID);
    layernorm_rows_k<<<MROWS, 256>>>(y, g1, be1, x1);

    // Hf = gelu(x1 @ W1 + b1) ; y2 = Hf @ W2 + b2 + x1 ; out = LN(y2)
    sgemm128<EPI_BIAS_GELU><<<dim3(MLPD / 128, MROWS / 128), 256>>>(x1, W1, Hf, b1, nullptr, MROWS, MLPD, HID);
    sgemm128<EPI_BIAS_RES><<<dim3(HID / 128, MROWS / 128), 256>>>(Hf, W2, y2, b2, x1, MROWS, HID, MLPD);
    layernorm_rows_k<<<MROWS, 256>>>(y2, g2, be2, out);
}